// round 16
// baseline (speedup 1.0000x reference)
#include <cuda_runtime.h>
#include <math.h>

#define FULLMASK 0xffffffffu
typedef unsigned long long u64;

// ---- packed f32x2 primitives (sm_103a; ptxas won't emit these from C++) ----
__device__ __forceinline__ u64 pk(float lo, float hi) {
  u64 r; asm("mov.b64 %0, {%1,%2};" : "=l"(r) : "f"(lo), "f"(hi)); return r;
}
__device__ __forceinline__ void unpk(u64 v, float& lo, float& hi) {
  asm("mov.b64 {%0,%1}, %2;" : "=f"(lo), "=f"(hi) : "l"(v));
}
__device__ __forceinline__ u64 f2fma(u64 a, u64 b, u64 c) {
  u64 d; asm("fma.rn.f32x2 %0, %1, %2, %3;" : "=l"(d) : "l"(a), "l"(b), "l"(c)); return d;
}
__device__ __forceinline__ u64 f2mul(u64 a, u64 b) {
  u64 d; asm("mul.rn.f32x2 %0, %1, %2;" : "=l"(d) : "l"(a), "l"(b)); return d;
}
__device__ __forceinline__ u64 f2add(u64 a, u64 b) {
  u64 d; asm("add.rn.f32x2 %0, %1, %2;" : "=l"(d) : "l"(a), "l"(b)); return d;
}

// ---------------------------------------------------------------------------
// Layout: 8 lanes per element (g = tid&7).
// Lane bits: q0 -> xor 1, q2 -> xor 2, q4 -> xor 4.  PACK AXIS: q6.
// k index: bit3=q1(8), bit2=q3(4), bit1=q5(2), bit0=q7(1).
// Same circuit algebra as the passing R15 kernel. New here (occupancy 6):
//  - __launch_bounds__(128, 6)
//  - uniform trig held ONLY as the per-lane (us, ucv) pair; all broadcast
//    floats re-shuffled on demand (L0/L1 entry, expval, head) to cut the
//    long-lived register set under the 85-reg cap.
// ---------------------------------------------------------------------------

template<int TMk>
__device__ __forceinline__ void ry_cnot_reg(u64 (&P)[16], u64 pa, u64 pb, u64 pg, u64 pd) {
#pragma unroll
  for (int k = 0; k < 16; ++k) if (!(k & TMk)) {
    u64 A = P[k], B = P[k + TMk];
    P[k]       = f2fma(pa, A, f2mul(pb, B));
    P[k + TMk] = f2fma(pg, A, f2mul(pd, B));
  }
}

template<int LM, int KM>
__device__ __forceinline__ void ry_lane_cnot_t(u64 (&P)[16], u64 tgg, u64 tggn) {
#pragma unroll
  for (int k = 0; k < 16; ++k) {
    u64 p = __shfl_xor_sync(FULLMASK, P[k], LM);
    if (k & KM) P[k] = f2fma(tggn, P[k], p);
    else        P[k] = f2fma(tgg, p, P[k]);
  }
}

template<int LM, int KM>
__device__ __forceinline__ void cnot_ry_lane_t(u64 (&P)[16], u64 tgg) {
#pragma unroll
  for (int k = 0; k < 16; ++k) {
    u64 p = __shfl_xor_sync(FULLMASK, P[k], LM);
    if (k & KM) P[k] = f2fma(tgg, P[k], p);
    else        P[k] = f2fma(tgg, p, P[k]);
  }
}

template<int TMk>
__device__ __forceinline__ void condswap(u64 (&P)[16], bool f) {
#pragma unroll
  for (int k = 0; k < 16; ++k) if (!(k & TMk)) {
    u64 A = P[k], B = P[k + TMk];
    P[k]       = f ? B : A;
    P[k + TMk] = f ? A : B;
  }
}

__device__ __forceinline__ void ry_pack_cnot56_s(u64 (&P)[16], float t6) {
#pragma unroll
  for (int k = 0; k < 16; ++k) {
    float l, h; unpk(P[k], l, h);
    float a = fmaf(-t6, h, l);
    float b = fmaf(t6, l, h);
    P[k] = (k & 2) ? pk(b, a) : pk(a, b);
  }
}

__device__ __forceinline__ void ry_q7_cnot67_s(u64 (&P)[16], float t7) {
#pragma unroll
  for (int k = 0; k < 16; k += 2) {
    float al, ah, bl, bh;
    unpk(P[k], al, ah); unpk(P[k + 1], bl, bh);
    float xl = fmaf(-t7, bl, al);
    float xh = fmaf(-t7, bh, ah);
    float yl = fmaf(t7, al, bl);
    float yh = fmaf(t7, ah, bh);
    P[k]     = pk(xl, yh);
    P[k + 1] = pk(yl, xh);
  }
}

#define CRXT_PAIR(Cr0, Ci0, Cr1, Ci1, thp, thn)                     \
  {                                                                 \
    u64 _r0 = (Cr0), _i0 = (Ci0), _r1 = (Cr1), _i1 = (Ci1);         \
    (Cr0) = f2fma((thp), _i1, _r0);                                 \
    (Ci0) = f2fma((thn), _r1, _i0);                                 \
    (Cr1) = f2fma((thp), _i0, _r1);                                 \
    (Ci1) = f2fma((thn), _r0, _i1);                                 \
  }

#define CRXT_PAIR2(Cr0, Ci0, Cr1, Ci1, tup, tun, tdp, tdn)          \
  {                                                                 \
    u64 _r0 = (Cr0), _i0 = (Ci0), _r1 = (Cr1), _i1 = (Ci1);         \
    (Cr0) = f2fma((tup), _i1, _r0);                                 \
    (Ci0) = f2fma((tun), _r1, _i0);                                 \
    (Cr1) = f2fma((tdp), _i0, _r1);                                 \
    (Ci1) = f2fma((tdn), _r0, _i1);                                 \
  }

#define U3T_PAIR(Cr0, Ci0, Cr1, Ci1, Arn, Aip, Ain, Cc_, Csn, Csp, Er_, Ein, Eip) \
  {                                                                             \
    u64 _r0 = (Cr0), _i0 = (Ci0), _r1 = (Cr1), _i1 = (Ci1);                     \
    (Cr0) = f2fma(Arn, _r1, f2fma(Aip, _i1, _r0));                              \
    (Ci0) = f2fma(Arn, _i1, f2fma(Ain, _r1, _i0));                              \
    (Cr1) = f2fma(Cc_, _r0, f2fma(Csn, _i0, f2fma(Er_, _r1, f2mul(Ein, _i1)))); \
    (Ci1) = f2fma(Cc_, _i0, f2fma(Csp, _r0, f2fma(Er_, _i1, f2mul(Eip, _r1)))); \
  }

__global__ void __launch_bounds__(128, 6)
qcnn_kernel(const float* __restrict__ x,
            const float* __restrict__ crx_theta,
            const float* __restrict__ u3_params,
            const float* __restrict__ w1,
            const float* __restrict__ b1,
            const float* __restrict__ w2,
            const float* __restrict__ b2,
            float* __restrict__ out, int B)
{
  int tid  = blockIdx.x * blockDim.x + threadIdx.x;
  int elem = tid >> 3;
  if (elem >= B) return;
  int g = tid & 7;
  bool g0 = (g & 1) != 0;
  bool g1 = (g & 2) != 0;
  bool g2 = (g & 4) != 0;

  // --- per-element angles ---
  float myx = x[elem * 8 + g];
  float ms, mc;
  sincosf(0.5f * myx, &ms, &mc);
  float mt = __fdividef(ms, mc);

  // --- uniform trig: ONE sincosf per lane (launch-uniform params) ---
  // lane 0: 0.5*crx0 | 1: 0.5*crx1 | 2: 0.5*uth0 | 3: uph0 | 4: ulm0
  // lane 5: 0.5*uth1 | 6: uph1 | 7: ulm1
  // Held ONLY as (us, ucv); broadcast on demand later.
  float us, ucv;
  {
    float ua = (g < 2) ? 0.5f * crx_theta[g] : u3_params[g - 2];
    if (g == 2 || g == 5) ua *= 0.5f;
    sincosf(ua, &us, &ucv);
  }

  float tq[8];
#pragma unroll
  for (int q = 0; q < 8; ++q) tq[q] = __shfl_sync(FULLMASK, mt, q, 8);

  u64 P[16];
  {
    float cq[8], sq[8];
#pragma unroll
    for (int q = 0; q < 8; ++q) {
      cq[q] = __shfl_sync(FULLMASK, mc, q, 8);
      sq[q] = __shfl_sync(FULLMASK, ms, q, 8);
    }
    float cprod = cq[0]*cq[1]*cq[2]*cq[3]*cq[4]*cq[5]*cq[6]*cq[7];
    float F = cprod * cprod * cprod;

    float b[16];
    b[0] = F * (g0 ? sq[0] : cq[0]) * (g1 ? sq[2] : cq[2]) * (g2 ? sq[4] : cq[4]);
#pragma unroll
    for (int i = 0; i < 1; ++i) { b[i+1] = b[i]*sq[7]; b[i] *= cq[7]; }
#pragma unroll
    for (int i = 0; i < 2; ++i) { b[i+2] = b[i]*sq[5]; b[i] *= cq[5]; }
#pragma unroll
    for (int i = 0; i < 4; ++i) { b[i+4] = b[i]*sq[3]; b[i] *= cq[3]; }
    {
      float f_lo = g0 ? sq[1] : cq[1];
      float f_hi = g0 ? cq[1] : sq[1];
#pragma unroll
      for (int i = 0; i < 8; ++i) { b[i+8] = b[i]*f_hi; b[i] *= f_lo; }
    }

    u64 c6s6 = pk(cq[6], sq[6]);
#pragma unroll
    for (int k = 0; k < 16; ++k) P[k] = f2mul(pk(b[k], b[k]), c6s6);
  }

  float tg0 = g0 ? tq[0] : -tq[0];
  float tg2 = g1 ? tq[2] : -tq[2];
  float tg4 = g2 ? tq[4] : -tq[4];

  // cycle 1 CNOT ring; (0,1) pre-applied, (7,0) deferred into cycle 2.
#pragma unroll
  for (int k = 0; k < 16; ++k) if (k & 8)
    P[k] = __shfl_xor_sync(FULLMASK, P[k], 2);
  condswap<4>(P, g1);
#pragma unroll
  for (int k = 0; k < 16; ++k) if (k & 4)
    P[k] = __shfl_xor_sync(FULLMASK, P[k], 4);
  condswap<2>(P, g2);
#pragma unroll
  for (int k = 0; k < 16; k += 2) {
    float l0, h0, l1, h1;
    unpk(P[k], l0, h0); unpk(P[k+1], l1, h1);
    if (k & 2) { P[k] = pk(h0, l1); P[k+1] = pk(h1, l0); }
    else       { P[k] = pk(l0, h1); P[k+1] = pk(l1, h0); }
  }

  // --- cycles 2..4 (tan form; RY+CNOT fused everywhere) ---
  {
    u64 tgg0 = pk(tg0, tg0);
    u64 tgg2 = pk(tg2, tg2), tgg2n = pk(-tg2, -tg2);
    u64 tgg4 = pk(tg4, tg4), tgg4n = pk(-tg4, -tg4);

    float t1 = tq[1], t3 = tq[3], t5 = tq[5];
    u64 a1 = pk(g0?t1:1.f, g0?t1:1.f),  b1p = pk(g0?1.f:-t1, g0?1.f:-t1);
    u64 g1p = pk(g0?1.f:t1, g0?1.f:t1), d1 = pk(g0?-t1:1.f, g0?-t1:1.f);
    u64 a3 = pk(g1?t3:1.f, g1?t3:1.f),  b3p = pk(g1?1.f:-t3, g1?1.f:-t3);
    u64 g3p = pk(g1?1.f:t3, g1?1.f:t3), d3 = pk(g1?-t3:1.f, g1?-t3:1.f);
    u64 a5 = pk(g2?t5:1.f, g2?t5:1.f),  b5p = pk(g2?1.f:-t5, g2?1.f:-t5);
    u64 g5p = pk(g2?1.f:t5, g2?1.f:t5), d5 = pk(g2?-t5:1.f, g2?-t5:1.f);

    float t6 = tq[6], t7 = tq[7];

#pragma unroll
    for (int cy = 0; cy < 3; ++cy) {
      cnot_ry_lane_t<1, 1>(P, tgg0);               // CNOT(7,0)[prev] + RY q0
      ry_cnot_reg<8>(P, a1, b1p, g1p, d1);         // RY q1 + CNOT(0,1)
      ry_lane_cnot_t<2, 8>(P, tgg2, tgg2n);        // RY q2 + CNOT(1,2)
      ry_cnot_reg<4>(P, a3, b3p, g3p, d3);         // RY q3 + CNOT(2,3)
      ry_lane_cnot_t<4, 4>(P, tgg4, tgg4n);        // RY q4 + CNOT(3,4)
      ry_cnot_reg<2>(P, a5, b5p, g5p, d5);         // RY q5 + CNOT(4,5)
      ry_pack_cnot56_s(P, t6);                     // RY q6 + CNOT(5,6)
      ry_q7_cnot67_s(P, t7);                       // RY q7 + CNOT(6,7)
    }
  }

  // final standalone CNOT(7,0)
#pragma unroll
  for (int k = 0; k < 16; ++k) if (k & 1)
    P[k] = __shfl_xor_sync(FULLMASK, P[k], 1);

  // =================== LAYER PHASE (same algebra as R15) ===================
  u64 Cr[16], Ci[16];

  // --- layer 0 ---
  {
    float sh = __shfl_sync(FULLMASK, us, 0, 8);
    float cc = __shfl_sync(FULLMASK, ucv, 0, 8);
    float t0 = __fdividef(sh, cc);
    float t0u = sh;                          // t0 * c0 (exact)
    float t0d = __fdividef(sh, cc * cc);     // t0 / c0

    // CRX(0,1) on REAL state (tan).
    {
      float thl = g0 ? -t0 : 0.0f;
      u64 thlp = pk(thl, thl);
#pragma unroll
      for (int k = 0; k < 16; ++k) {
        Cr[k] = P[k];
        Ci[k] = f2mul(thlp, P[k ^ 8]);
      }
    }

    // CRX(2,3)
    {
      float thl = g1 ? t0 : 0.0f;
      u64 tp = pk(thl, thl), tn = pk(-thl, -thl);
#pragma unroll
      for (int k = 0; k < 16; ++k) if (!(k & 4))
        CRXT_PAIR(Cr[k], Ci[k], Cr[k+4], Ci[k+4], tp, tn);
    }

    // CRX(4,5)
    {
      float thl = g2 ? t0 : 0.0f;
      u64 tp = pk(thl, thl), tn = pk(-thl, -thl);
#pragma unroll
      for (int k = 0; k < 16; ++k) if (!(k & 2))
        CRXT_PAIR(Cr[k], Ci[k], Cr[k+2], Ci[k+2], tp, tn);
    }

    // CRX(6,7): masked th = (0, t0).
    {
      u64 tp = pk(0.0f, t0), tn = pk(0.0f, -t0);
#pragma unroll
      for (int k = 0; k < 16; ++k) if (!(k & 1))
        CRXT_PAIR(Cr[k], Ci[k], Cr[k+1], Ci[k+1], tp, tn);
    }

    // CRX(1,2)
    {
      float th12 = g1 ? t0d : t0u;
      u64 tp = pk(th12, th12), tn = pk(-th12, -th12);
#pragma unroll
      for (int k = 0; k < 16; ++k) if (k & 8) {
        u64 pr = __shfl_xor_sync(FULLMASK, Cr[k], 2);
        u64 pi = __shfl_xor_sync(FULLMASK, Ci[k], 2);
        Cr[k] = f2fma(tp, pi, Cr[k]);
        Ci[k] = f2fma(tn, pr, Ci[k]);
      }
    }

    // CRX(3,4)
    {
      float th34 = g2 ? t0d : t0u;
      u64 tp = pk(th34, th34), tn = pk(-th34, -th34);
#pragma unroll
      for (int k = 0; k < 16; ++k) if (k & 4) {
        u64 pr = __shfl_xor_sync(FULLMASK, Cr[k], 4);
        u64 pi = __shfl_xor_sync(FULLMASK, Ci[k], 4);
        Cr[k] = f2fma(tp, pi, Cr[k]);
        Ci[k] = f2fma(tn, pr, Ci[k]);
      }
    }

    // CRX(5,6): scalar slot ths (t0*c0, t0/c0).
#pragma unroll
    for (int k = 0; k < 16; ++k) if (k & 2) {
      float rl, rh, il, ih;
      unpk(Cr[k], rl, rh); unpk(Ci[k], il, ih);
      float nrl = fmaf(t0u, ih, rl);
      float nrh = fmaf(t0d, il, rh);
      float nil = fmaf(-t0u, rh, il);
      float nih = fmaf(-t0d, rl, ih);
      Cr[k] = pk(nrl, nrh);
      Ci[k] = pk(nil, nih);
    }

    // U3(layer 0), tan form (broadcast trig on demand).
    {
      float st0  = __shfl_sync(FULLMASK, us, 2, 8);
      float ct0  = __shfl_sync(FULLMASK, ucv, 2, 8);
      float sph0 = __shfl_sync(FULLMASK, us, 3, 8);
      float cph0 = __shfl_sync(FULLMASK, ucv, 3, 8);
      float slm0 = __shfl_sync(FULLMASK, us, 4, 8);
      float clm0 = __shfl_sync(FULLMASK, ucv, 4, 8);
      float tu = __fdividef(st0, ct0);
      float cpl = cph0 * clm0 - sph0 * slm0;   // cos(uph0+ulm0)
      float spl = sph0 * clm0 + cph0 * slm0;   // sin(uph0+ulm0)
      float Ar = clm0 * tu, Ai = slm0 * tu;
      float Cc = cph0 * tu, Cs = sph0 * tu;
      float Er = cpl,       Ei = spl;
      u64 pCc = pk(Cc, Cc), pCsn = pk(-Cs, -Cs), pCsp = pk(Cs, Cs);
      {
        float Ars = Ar * cc, Ais = Ai * cc, Ers = Er * cc, Eis = Ei * cc;
        u64 sArn = pk(-Ars, -Ars), sAip = pk(Ais, Ais), sAin = pk(-Ais, -Ais);
        u64 sEr = pk(Ers, Ers), sEin = pk(-Eis, -Eis), sEip = pk(Eis, Eis);
#pragma unroll
        for (int k = 0; k < 16; ++k) if (!(k & 8))
          U3T_PAIR(Cr[k], Ci[k], Cr[k+8], Ci[k+8],
                   sArn, sAip, sAin, pCc, pCsn, pCsp, sEr, sEin, sEip);
#pragma unroll
        for (int k = 0; k < 16; ++k) if (!(k & 4))
          U3T_PAIR(Cr[k], Ci[k], Cr[k+4], Ci[k+4],
                   sArn, sAip, sAin, pCc, pCsn, pCsp, sEr, sEin, sEip);
#pragma unroll
        for (int k = 0; k < 16; ++k) if (!(k & 2))
          U3T_PAIR(Cr[k], Ci[k], Cr[k+2], Ci[k+2],
                   sArn, sAip, sAin, pCc, pCsn, pCsp, sEr, sEin, sEip);
      }
      {
        u64 uArn = pk(-Ar, -Ar), uAip = pk(Ai, Ai), uAin = pk(-Ai, -Ai);
        u64 uEr = pk(Er, Er), uEin = pk(-Ei, -Ei), uEip = pk(Ei, Ei);
#pragma unroll
        for (int k = 0; k < 16; ++k) if (!(k & 1))
          U3T_PAIR(Cr[k], Ci[k], Cr[k+1], Ci[k+1],
                   uArn, uAip, uAin, pCc, pCsn, pCsp, uEr, uEin, uEip);
      }
    }
  }

  // --- layer 1 ---
  {
    float sh = __shfl_sync(FULLMASK, us, 1, 8);
    float cc = __shfl_sync(FULLMASK, ucv, 1, 8);
    float t1 = __fdividef(sh, cc);
    float t1u = sh;
    float t1d = __fdividef(sh, cc * cc);
    u64 tp = pk(t1, t1), tn = pk(-t1, -t1);

#pragma unroll
    for (int k = 0; k < 16; ++k) if ((k & 8) && !(k & 4))     // CRX(1,3)
      CRXT_PAIR(Cr[k], Ci[k], Cr[k+4], Ci[k+4], tp, tn);
#pragma unroll
    for (int k = 0; k < 16; ++k) if ((k & 2) && !(k & 1))     // CRX(5,7)
      CRXT_PAIR(Cr[k], Ci[k], Cr[k+1], Ci[k+1], tp, tn);
    {
      u64 tup = pk(t1u, t1u), tun = pk(-t1u, -t1u);
      u64 tdp = pk(t1d, t1d), tdn = pk(-t1d, -t1d);
#pragma unroll
      for (int k = 0; k < 16; ++k) if ((k & 4) && !(k & 2))   // CRX(3,5)
        CRXT_PAIR2(Cr[k], Ci[k], Cr[k+2], Ci[k+2], tup, tun, tdp, tdn);
    }

    {
      float st1  = __shfl_sync(FULLMASK, us, 5, 8);
      float ct1  = __shfl_sync(FULLMASK, ucv, 5, 8);
      float sph1 = __shfl_sync(FULLMASK, us, 6, 8);
      float cph1 = __shfl_sync(FULLMASK, ucv, 6, 8);
      float slm1 = __shfl_sync(FULLMASK, us, 7, 8);
      float clm1 = __shfl_sync(FULLMASK, ucv, 7, 8);
      float tu = __fdividef(st1, ct1);
      float cpl = cph1 * clm1 - sph1 * slm1;
      float spl = sph1 * clm1 + cph1 * slm1;
      float Ar = clm1 * tu, Ai = slm1 * tu;
      float Cc = cph1 * tu, Cs = sph1 * tu;
      float Er = cpl,       Ei = spl;
      u64 pCc = pk(Cc, Cc), pCsn = pk(-Cs, -Cs), pCsp = pk(Cs, Cs);
      {
        float Ars = Ar * cc, Ais = Ai * cc, Ers = Er * cc, Eis = Ei * cc;
        u64 sArn = pk(-Ars, -Ars), sAip = pk(Ais, Ais), sAin = pk(-Ais, -Ais);
        u64 sEr = pk(Ers, Ers), sEin = pk(-Eis, -Eis), sEip = pk(Eis, Eis);
#pragma unroll
        for (int k = 0; k < 16; ++k) if (!(k & 4))            // U3 q3 (scaled)
          U3T_PAIR(Cr[k], Ci[k], Cr[k+4], Ci[k+4],
                   sArn, sAip, sAin, pCc, pCsn, pCsp, sEr, sEin, sEip);
      }
      {
        u64 uArn = pk(-Ar, -Ar), uAip = pk(Ai, Ai), uAin = pk(-Ai, -Ai);
        u64 uEr = pk(Er, Er), uEin = pk(-Ei, -Ei), uEip = pk(Ei, Ei);
#pragma unroll
        for (int k = 0; k < 16; ++k) if (!(k & 1))            // U3 q7
          U3T_PAIR(Cr[k], Ci[k], Cr[k+1], Ci[k+1],
                   uArn, uAip, uAin, pCc, pCsn, pCsp, uEr, uEin, uEip);
      }
    }
  }

  // --- expval with deferred weights (trig re-broadcast) ---
  float cc1e = __shfl_sync(FULLMASK, ucv, 1, 8);
  float c1sq = cc1e * cc1e;
  float c1q  = c1sq * c1sq;
  u64 pc2 = pk(c1sq, c1sq), pc4 = pk(c1q, c1q);

  u64 acc0 = pk(0.f, 0.f), acc1 = acc0, acc2 = acc0, acc3 = acc0;
#pragma unroll
  for (int k = 0; k < 16; ++k) {
    u64 pp = f2fma(Cr[k], Cr[k], f2mul(Ci[k], Ci[k]));
    const int nb = ((k >> 3) & 1) + ((k >> 1) & 1);
    if (nb == 1)      pp = f2mul(pp, pc2);
    else if (nb == 2) pp = f2mul(pp, pc4);
    int idx = ((k & 4) ? 2 : 0) | (k & 1);
    if      (idx == 0) acc0 = f2add(acc0, pp);
    else if (idx == 1) acc1 = f2add(acc1, pp);
    else if (idx == 2) acc2 = f2add(acc2, pp);
    else               acc3 = f2add(acc3, pp);
  }
  float cc0e = __shfl_sync(FULLMASK, ucv, 0, 8);
  float c02 = cc0e * cc0e;
  float l, h, s0, s1, s2, s3;
  unpk(acc0, l, h); s0 = fmaf(c02, h, l);
  unpk(acc1, l, h); s1 = fmaf(c02, h, l);
  unpk(acc2, l, h); s2 = fmaf(c02, h, l);
  unpk(acc3, l, h); s3 = fmaf(c02, h, l);
  float z3 = (s0 + s1) - (s2 + s3);
  float z7 = (s0 + s2) - (s1 + s3);

  {
    float lw2 = 1.0f;
    if (g0) lw2 *= c02;
    if (g1) lw2 *= c02;
    if (g2) lw2 *= c02;
    z3 *= lw2;
    z7 *= lw2;
  }

  z3 += __shfl_xor_sync(FULLMASK, z3, 1);
  z3 += __shfl_xor_sync(FULLMASK, z3, 2);
  z3 += __shfl_xor_sync(FULLMASK, z3, 4);
  z7 += __shfl_xor_sync(FULLMASK, z7, 1);
  z7 += __shfl_xor_sync(FULLMASK, z7, 2);
  z7 += __shfl_xor_sync(FULLMASK, z7, 4);

  // --- MLP head, parallel over the 8 group lanes ---
  {
    float ct0h = __shfl_sync(FULLMASK, ucv, 2, 8);
    float ct1h = __shfl_sync(FULLMASK, ucv, 5, 8);
    float ct0sq = ct0h * ct0h;
    float Gs = ct0sq * ct0sq * ct1h * ct1h;
    float G2 = Gs * Gs;
    z3 *= G2;
    z7 *= G2;

    int j = g;
    float hh = tanhf(fmaf(z3, w1[j], fmaf(z7, w1[10 + j], b1[j])));
    float part = hh * w2[j];
    if (g < 2) {
      int j2 = 8 + g;
      float hh2 = tanhf(fmaf(z3, w1[j2], fmaf(z7, w1[10 + j2], b1[j2])));
      part = fmaf(hh2, w2[j2], part);
    }
    part += __shfl_xor_sync(FULLMASK, part, 1);
    part += __shfl_xor_sync(FULLMASK, part, 2);
    part += __shfl_xor_sync(FULLMASK, part, 4);

    if (g == 0)
      out[elem] = 1.0f / (1.0f + expf(-(part + b2[0])));
  }
}

extern "C" void kernel_launch(void* const* d_in, const int* in_sizes, int n_in,
                              void* d_out, int out_size) {
  const float* x   = (const float*)d_in[0];
  const float* crx = (const float*)d_in[1];
  const float* u3p = (const float*)d_in[2];
  const float* w1  = (const float*)d_in[3];
  const float* b1  = (const float*)d_in[4];
  const float* w2  = (const float*)d_in[5];
  const float* b2  = (const float*)d_in[6];
  float* out = (float*)d_out;

  int B = in_sizes[0] / 8;
  int threads = B * 8;
  int block = 128;
  int grid = (threads + block - 1) / block;
  qcnn_kernel<<<grid, block>>>(x, crx, u3p, w1, b1, w2, b2, out, B);
}

// round 17
// speedup vs baseline: 1.0677x; 1.0677x over previous
#include <cuda_runtime.h>
#include <math.h>

#define FULLMASK 0xffffffffu
typedef unsigned long long u64;

// ---- packed f32x2 primitives (sm_103a; ptxas won't emit these from C++) ----
__device__ __forceinline__ u64 pk(float lo, float hi) {
  u64 r; asm("mov.b64 %0, {%1,%2};" : "=l"(r) : "f"(lo), "f"(hi)); return r;
}
__device__ __forceinline__ void unpk(u64 v, float& lo, float& hi) {
  asm("mov.b64 {%0,%1}, %2;" : "=f"(lo), "=f"(hi) : "l"(v));
}
__device__ __forceinline__ u64 f2fma(u64 a, u64 b, u64 c) {
  u64 d; asm("fma.rn.f32x2 %0, %1, %2, %3;" : "=l"(d) : "l"(a), "l"(b), "l"(c)); return d;
}
__device__ __forceinline__ u64 f2mul(u64 a, u64 b) {
  u64 d; asm("mul.rn.f32x2 %0, %1, %2;" : "=l"(d) : "l"(a), "l"(b)); return d;
}
__device__ __forceinline__ u64 f2add(u64 a, u64 b) {
  u64 d; asm("add.rn.f32x2 %0, %1, %2;" : "=l"(d) : "l"(a), "l"(b)); return d;
}

// ---------------------------------------------------------------------------
// Uniform-constant table (computed once by a 1-thread setup kernel).
// Indices:
//  0:t0 1:t0u 2:t0d
//  3:Ar0 4:Ai0 5:Cc0 6:Cs0 7:Er0 8:Ei0
//  9:Ars0 10:Ais0 11:Ers0 12:Eis0
//  13:t1 14:t1u 15:t1d
//  16:Ar1 17:Ai1 18:Cc1 19:Cs1 20:Er1 21:Ei1
//  22:Ars1 23:Ais1 24:Ers1 25:Eis1
//  26:c02 27:c1sq 28:c1q 29:G2
// ---------------------------------------------------------------------------
__device__ float g_uc[32];

__global__ void qcnn_setup(const float* __restrict__ crx_theta,
                           const float* __restrict__ u3_params) {
  // single thread
  float s0, c0; sincosf(0.5f * crx_theta[0], &s0, &c0);
  float s1, c1; sincosf(0.5f * crx_theta[1], &s1, &c1);
  g_uc[0] = __fdividef(s0, c0);
  g_uc[1] = s0;
  g_uc[2] = __fdividef(s0, c0 * c0);
  g_uc[13] = __fdividef(s1, c1);
  g_uc[14] = s1;
  g_uc[15] = __fdividef(s1, c1 * c1);

  float ct0, st0; sincosf(0.5f * u3_params[0], &st0, &ct0);
  float sph0, cph0; sincosf(u3_params[1], &sph0, &cph0);
  float slm0, clm0; sincosf(u3_params[2], &slm0, &clm0);
  float tu0 = __fdividef(st0, ct0);
  float cpl0 = cph0 * clm0 - sph0 * slm0;
  float spl0 = sph0 * clm0 + cph0 * slm0;
  float Ar0 = clm0 * tu0, Ai0 = slm0 * tu0;
  float Cc0 = cph0 * tu0, Cs0 = sph0 * tu0;
  g_uc[3] = Ar0;  g_uc[4] = Ai0;  g_uc[5] = Cc0;  g_uc[6] = Cs0;
  g_uc[7] = cpl0; g_uc[8] = spl0;
  g_uc[9]  = Ar0 * c0;  g_uc[10] = Ai0 * c0;
  g_uc[11] = cpl0 * c0; g_uc[12] = spl0 * c0;

  float ct1, st1; sincosf(0.5f * u3_params[3], &st1, &ct1);
  float sph1, cph1; sincosf(u3_params[4], &sph1, &cph1);
  float slm1, clm1; sincosf(u3_params[5], &slm1, &clm1);
  float tu1 = __fdividef(st1, ct1);
  float cpl1 = cph1 * clm1 - sph1 * slm1;
  float spl1 = sph1 * clm1 + cph1 * slm1;
  float Ar1 = clm1 * tu1, Ai1 = slm1 * tu1;
  float Cc1 = cph1 * tu1, Cs1 = sph1 * tu1;
  g_uc[16] = Ar1;  g_uc[17] = Ai1;  g_uc[18] = Cc1;  g_uc[19] = Cs1;
  g_uc[20] = cpl1; g_uc[21] = spl1;
  g_uc[22] = Ar1 * c1;  g_uc[23] = Ai1 * c1;
  g_uc[24] = cpl1 * c1; g_uc[25] = spl1 * c1;

  float c02 = c0 * c0;
  float c1sq = c1 * c1;
  g_uc[26] = c02;
  g_uc[27] = c1sq;
  g_uc[28] = c1sq * c1sq;
  float ct0sq = ct0 * ct0;
  float Gs = ct0sq * ct0sq * ct1 * ct1;
  g_uc[29] = Gs * Gs;
}

// ---------------------------------------------------------------------------
// Layout: 8 lanes per element (g = tid&7).
// Lane bits: q0 -> xor 1, q2 -> xor 2, q4 -> xor 4.  PACK AXIS: q6.
// k index: bit3=q1(8), bit2=q3(4), bit1=q5(2), bit0=q7(1).
// Same circuit algebra as the passing R15 kernel; uniform constants now come
// from g_uc (rematerializable loads -> no spills at occupancy 6).
// ---------------------------------------------------------------------------

template<int TMk>
__device__ __forceinline__ void ry_cnot_reg(u64 (&P)[16], u64 pa, u64 pb, u64 pg, u64 pd) {
#pragma unroll
  for (int k = 0; k < 16; ++k) if (!(k & TMk)) {
    u64 A = P[k], B = P[k + TMk];
    P[k]       = f2fma(pa, A, f2mul(pb, B));
    P[k + TMk] = f2fma(pg, A, f2mul(pd, B));
  }
}

template<int LM, int KM>
__device__ __forceinline__ void ry_lane_cnot_t(u64 (&P)[16], u64 tgg, u64 tggn) {
#pragma unroll
  for (int k = 0; k < 16; ++k) {
    u64 p = __shfl_xor_sync(FULLMASK, P[k], LM);
    if (k & KM) P[k] = f2fma(tggn, P[k], p);
    else        P[k] = f2fma(tgg, p, P[k]);
  }
}

template<int LM, int KM>
__device__ __forceinline__ void cnot_ry_lane_t(u64 (&P)[16], u64 tgg) {
#pragma unroll
  for (int k = 0; k < 16; ++k) {
    u64 p = __shfl_xor_sync(FULLMASK, P[k], LM);
    if (k & KM) P[k] = f2fma(tgg, P[k], p);
    else        P[k] = f2fma(tgg, p, P[k]);
  }
}

template<int TMk>
__device__ __forceinline__ void condswap(u64 (&P)[16], bool f) {
#pragma unroll
  for (int k = 0; k < 16; ++k) if (!(k & TMk)) {
    u64 A = P[k], B = P[k + TMk];
    P[k]       = f ? B : A;
    P[k + TMk] = f ? A : B;
  }
}

__device__ __forceinline__ void ry_pack_cnot56_s(u64 (&P)[16], float t6) {
#pragma unroll
  for (int k = 0; k < 16; ++k) {
    float l, h; unpk(P[k], l, h);
    float a = fmaf(-t6, h, l);
    float b = fmaf(t6, l, h);
    P[k] = (k & 2) ? pk(b, a) : pk(a, b);
  }
}

__device__ __forceinline__ void ry_q7_cnot67_s(u64 (&P)[16], float t7) {
#pragma unroll
  for (int k = 0; k < 16; k += 2) {
    float al, ah, bl, bh;
    unpk(P[k], al, ah); unpk(P[k + 1], bl, bh);
    float xl = fmaf(-t7, bl, al);
    float xh = fmaf(-t7, bh, ah);
    float yl = fmaf(t7, al, bl);
    float yh = fmaf(t7, ah, bh);
    P[k]     = pk(xl, yh);
    P[k + 1] = pk(yl, xh);
  }
}

#define CRXT_PAIR(Cr0, Ci0, Cr1, Ci1, thp, thn)                     \
  {                                                                 \
    u64 _r0 = (Cr0), _i0 = (Ci0), _r1 = (Cr1), _i1 = (Ci1);         \
    (Cr0) = f2fma((thp), _i1, _r0);                                 \
    (Ci0) = f2fma((thn), _r1, _i0);                                 \
    (Cr1) = f2fma((thp), _i0, _r1);                                 \
    (Ci1) = f2fma((thn), _r0, _i1);                                 \
  }

#define CRXT_PAIR2(Cr0, Ci0, Cr1, Ci1, tup, tun, tdp, tdn)          \
  {                                                                 \
    u64 _r0 = (Cr0), _i0 = (Ci0), _r1 = (Cr1), _i1 = (Ci1);         \
    (Cr0) = f2fma((tup), _i1, _r0);                                 \
    (Ci0) = f2fma((tun), _r1, _i0);                                 \
    (Cr1) = f2fma((tdp), _i0, _r1);                                 \
    (Ci1) = f2fma((tdn), _r0, _i1);                                 \
  }

#define U3T_PAIR(Cr0, Ci0, Cr1, Ci1, Arn, Aip, Ain, Cc_, Csn, Csp, Er_, Ein, Eip) \
  {                                                                             \
    u64 _r0 = (Cr0), _i0 = (Ci0), _r1 = (Cr1), _i1 = (Ci1);                     \
    (Cr0) = f2fma(Arn, _r1, f2fma(Aip, _i1, _r0));                              \
    (Ci0) = f2fma(Arn, _i1, f2fma(Ain, _r1, _i0));                              \
    (Cr1) = f2fma(Cc_, _r0, f2fma(Csn, _i0, f2fma(Er_, _r1, f2mul(Ein, _i1)))); \
    (Ci1) = f2fma(Cc_, _i0, f2fma(Csp, _r0, f2fma(Er_, _i1, f2mul(Eip, _r1)))); \
  }

__global__ void __launch_bounds__(128, 6)
qcnn_kernel(const float* __restrict__ x,
            const float* __restrict__ w1,
            const float* __restrict__ b1,
            const float* __restrict__ w2,
            const float* __restrict__ b2,
            float* __restrict__ out, int B)
{
  int tid  = blockIdx.x * blockDim.x + threadIdx.x;
  int elem = tid >> 3;
  if (elem >= B) return;
  int g = tid & 7;
  bool g0 = (g & 1) != 0;
  bool g1 = (g & 2) != 0;
  bool g2 = (g & 4) != 0;

  // --- per-element angles ---
  float myx = x[elem * 8 + g];
  float ms, mc;
  sincosf(0.5f * myx, &ms, &mc);
  float mt = __fdividef(ms, mc);

  float tq[8];
#pragma unroll
  for (int q = 0; q < 8; ++q) tq[q] = __shfl_sync(FULLMASK, mt, q, 8);

  u64 P[16];
  {
    float cq[8], sq[8];
#pragma unroll
    for (int q = 0; q < 8; ++q) {
      cq[q] = __shfl_sync(FULLMASK, mc, q, 8);
      sq[q] = __shfl_sync(FULLMASK, ms, q, 8);
    }
    float cprod = cq[0]*cq[1]*cq[2]*cq[3]*cq[4]*cq[5]*cq[6]*cq[7];
    float F = cprod * cprod * cprod;

    float b[16];
    b[0] = F * (g0 ? sq[0] : cq[0]) * (g1 ? sq[2] : cq[2]) * (g2 ? sq[4] : cq[4]);
#pragma unroll
    for (int i = 0; i < 1; ++i) { b[i+1] = b[i]*sq[7]; b[i] *= cq[7]; }
#pragma unroll
    for (int i = 0; i < 2; ++i) { b[i+2] = b[i]*sq[5]; b[i] *= cq[5]; }
#pragma unroll
    for (int i = 0; i < 4; ++i) { b[i+4] = b[i]*sq[3]; b[i] *= cq[3]; }
    {
      float f_lo = g0 ? sq[1] : cq[1];
      float f_hi = g0 ? cq[1] : sq[1];
#pragma unroll
      for (int i = 0; i < 8; ++i) { b[i+8] = b[i]*f_hi; b[i] *= f_lo; }
    }

    u64 c6s6 = pk(cq[6], sq[6]);
#pragma unroll
    for (int k = 0; k < 16; ++k) P[k] = f2mul(pk(b[k], b[k]), c6s6);
  }

  float tg0 = g0 ? tq[0] : -tq[0];
  float tg2 = g1 ? tq[2] : -tq[2];
  float tg4 = g2 ? tq[4] : -tq[4];

  // cycle 1 CNOT ring; (0,1) pre-applied, (7,0) deferred into cycle 2.
#pragma unroll
  for (int k = 0; k < 16; ++k) if (k & 8)
    P[k] = __shfl_xor_sync(FULLMASK, P[k], 2);
  condswap<4>(P, g1);
#pragma unroll
  for (int k = 0; k < 16; ++k) if (k & 4)
    P[k] = __shfl_xor_sync(FULLMASK, P[k], 4);
  condswap<2>(P, g2);
#pragma unroll
  for (int k = 0; k < 16; k += 2) {
    float l0, h0, l1, h1;
    unpk(P[k], l0, h0); unpk(P[k+1], l1, h1);
    if (k & 2) { P[k] = pk(h0, l1); P[k+1] = pk(h1, l0); }
    else       { P[k] = pk(l0, h1); P[k+1] = pk(l1, h0); }
  }

  // --- cycles 2..4 (tan form; RY+CNOT fused everywhere) ---
  {
    u64 tgg0 = pk(tg0, tg0);
    u64 tgg2 = pk(tg2, tg2), tgg2n = pk(-tg2, -tg2);
    u64 tgg4 = pk(tg4, tg4), tgg4n = pk(-tg4, -tg4);

    float t1 = tq[1], t3 = tq[3], t5 = tq[5];
    u64 a1 = pk(g0?t1:1.f, g0?t1:1.f),  b1p = pk(g0?1.f:-t1, g0?1.f:-t1);
    u64 g1p = pk(g0?1.f:t1, g0?1.f:t1), d1 = pk(g0?-t1:1.f, g0?-t1:1.f);
    u64 a3 = pk(g1?t3:1.f, g1?t3:1.f),  b3p = pk(g1?1.f:-t3, g1?1.f:-t3);
    u64 g3p = pk(g1?1.f:t3, g1?1.f:t3), d3 = pk(g1?-t3:1.f, g1?-t3:1.f);
    u64 a5 = pk(g2?t5:1.f, g2?t5:1.f),  b5p = pk(g2?1.f:-t5, g2?1.f:-t5);
    u64 g5p = pk(g2?1.f:t5, g2?1.f:t5), d5 = pk(g2?-t5:1.f, g2?-t5:1.f);

    float t6 = tq[6], t7 = tq[7];

#pragma unroll
    for (int cy = 0; cy < 3; ++cy) {
      cnot_ry_lane_t<1, 1>(P, tgg0);               // CNOT(7,0)[prev] + RY q0
      ry_cnot_reg<8>(P, a1, b1p, g1p, d1);         // RY q1 + CNOT(0,1)
      ry_lane_cnot_t<2, 8>(P, tgg2, tgg2n);        // RY q2 + CNOT(1,2)
      ry_cnot_reg<4>(P, a3, b3p, g3p, d3);         // RY q3 + CNOT(2,3)
      ry_lane_cnot_t<4, 4>(P, tgg4, tgg4n);        // RY q4 + CNOT(3,4)
      ry_cnot_reg<2>(P, a5, b5p, g5p, d5);         // RY q5 + CNOT(4,5)
      ry_pack_cnot56_s(P, t6);                     // RY q6 + CNOT(5,6)
      ry_q7_cnot67_s(P, t7);                       // RY q7 + CNOT(6,7)
    }
  }

  // final standalone CNOT(7,0)
#pragma unroll
  for (int k = 0; k < 16; ++k) if (k & 1)
    P[k] = __shfl_xor_sync(FULLMASK, P[k], 1);

  // =================== LAYER PHASE =========================================
  u64 Cr[16], Ci[16];

  // --- layer 0 ---
  {
    float t0  = __ldg(&g_uc[0]);
    float t0u = __ldg(&g_uc[1]);
    float t0d = __ldg(&g_uc[2]);

    // CRX(0,1) on REAL state (tan).
    {
      float thl = g0 ? -t0 : 0.0f;
      u64 thlp = pk(thl, thl);
#pragma unroll
      for (int k = 0; k < 16; ++k) {
        Cr[k] = P[k];
        Ci[k] = f2mul(thlp, P[k ^ 8]);
      }
    }

    // CRX(2,3)
    {
      float thl = g1 ? t0 : 0.0f;
      u64 tp = pk(thl, thl), tn = pk(-thl, -thl);
#pragma unroll
      for (int k = 0; k < 16; ++k) if (!(k & 4))
        CRXT_PAIR(Cr[k], Ci[k], Cr[k+4], Ci[k+4], tp, tn);
    }

    // CRX(4,5)
    {
      float thl = g2 ? t0 : 0.0f;
      u64 tp = pk(thl, thl), tn = pk(-thl, -thl);
#pragma unroll
      for (int k = 0; k < 16; ++k) if (!(k & 2))
        CRXT_PAIR(Cr[k], Ci[k], Cr[k+2], Ci[k+2], tp, tn);
    }

    // CRX(6,7): masked th = (0, t0).
    {
      u64 tp = pk(0.0f, t0), tn = pk(0.0f, -t0);
#pragma unroll
      for (int k = 0; k < 16; ++k) if (!(k & 1))
        CRXT_PAIR(Cr[k], Ci[k], Cr[k+1], Ci[k+1], tp, tn);
    }

    // CRX(1,2)
    {
      float th12 = g1 ? t0d : t0u;
      u64 tp = pk(th12, th12), tn = pk(-th12, -th12);
#pragma unroll
      for (int k = 0; k < 16; ++k) if (k & 8) {
        u64 pr = __shfl_xor_sync(FULLMASK, Cr[k], 2);
        u64 pi = __shfl_xor_sync(FULLMASK, Ci[k], 2);
        Cr[k] = f2fma(tp, pi, Cr[k]);
        Ci[k] = f2fma(tn, pr, Ci[k]);
      }
    }

    // CRX(3,4)
    {
      float th34 = g2 ? t0d : t0u;
      u64 tp = pk(th34, th34), tn = pk(-th34, -th34);
#pragma unroll
      for (int k = 0; k < 16; ++k) if (k & 4) {
        u64 pr = __shfl_xor_sync(FULLMASK, Cr[k], 4);
        u64 pi = __shfl_xor_sync(FULLMASK, Ci[k], 4);
        Cr[k] = f2fma(tp, pi, Cr[k]);
        Ci[k] = f2fma(tn, pr, Ci[k]);
      }
    }

    // CRX(5,6): scalar slot ths (t0*c0, t0/c0).
#pragma unroll
    for (int k = 0; k < 16; ++k) if (k & 2) {
      float rl, rh, il, ih;
      unpk(Cr[k], rl, rh); unpk(Ci[k], il, ih);
      float nrl = fmaf(t0u, ih, rl);
      float nrh = fmaf(t0d, il, rh);
      float nil = fmaf(-t0u, rh, il);
      float nih = fmaf(-t0d, rl, ih);
      Cr[k] = pk(nrl, nrh);
      Ci[k] = pk(nil, nih);
    }

    // U3(layer 0), tan form; scaled consts pre-multiplied in setup kernel.
    {
      float Ars = __ldg(&g_uc[9]),  Ais = __ldg(&g_uc[10]);
      float Ers = __ldg(&g_uc[11]), Eis = __ldg(&g_uc[12]);
      float Cc  = __ldg(&g_uc[5]),  Cs  = __ldg(&g_uc[6]);
      u64 pCc = pk(Cc, Cc), pCsn = pk(-Cs, -Cs), pCsp = pk(Cs, Cs);
      u64 sArn = pk(-Ars, -Ars), sAip = pk(Ais, Ais), sAin = pk(-Ais, -Ais);
      u64 sEr = pk(Ers, Ers), sEin = pk(-Eis, -Eis), sEip = pk(Eis, Eis);
#pragma unroll
      for (int k = 0; k < 16; ++k) if (!(k & 8))
        U3T_PAIR(Cr[k], Ci[k], Cr[k+8], Ci[k+8],
                 sArn, sAip, sAin, pCc, pCsn, pCsp, sEr, sEin, sEip);
#pragma unroll
      for (int k = 0; k < 16; ++k) if (!(k & 4))
        U3T_PAIR(Cr[k], Ci[k], Cr[k+4], Ci[k+4],
                 sArn, sAip, sAin, pCc, pCsn, pCsp, sEr, sEin, sEip);
#pragma unroll
      for (int k = 0; k < 16; ++k) if (!(k & 2))
        U3T_PAIR(Cr[k], Ci[k], Cr[k+2], Ci[k+2],
                 sArn, sAip, sAin, pCc, pCsn, pCsp, sEr, sEin, sEip);
    }
    {
      float Ar = __ldg(&g_uc[3]), Ai = __ldg(&g_uc[4]);
      float Er = __ldg(&g_uc[7]), Ei = __ldg(&g_uc[8]);
      float Cc = __ldg(&g_uc[5]), Cs = __ldg(&g_uc[6]);
      u64 pCc = pk(Cc, Cc), pCsn = pk(-Cs, -Cs), pCsp = pk(Cs, Cs);
      u64 uArn = pk(-Ar, -Ar), uAip = pk(Ai, Ai), uAin = pk(-Ai, -Ai);
      u64 uEr = pk(Er, Er), uEin = pk(-Ei, -Ei), uEip = pk(Ei, Ei);
#pragma unroll
      for (int k = 0; k < 16; ++k) if (!(k & 1))
        U3T_PAIR(Cr[k], Ci[k], Cr[k+1], Ci[k+1],
                 uArn, uAip, uAin, pCc, pCsn, pCsp, uEr, uEin, uEip);
    }
  }

  // --- layer 1 ---
  {
    float t1  = __ldg(&g_uc[13]);
    float t1u = __ldg(&g_uc[14]);
    float t1d = __ldg(&g_uc[15]);
    u64 tp = pk(t1, t1), tn = pk(-t1, -t1);

#pragma unroll
    for (int k = 0; k < 16; ++k) if ((k & 8) && !(k & 4))     // CRX(1,3)
      CRXT_PAIR(Cr[k], Ci[k], Cr[k+4], Ci[k+4], tp, tn);
#pragma unroll
    for (int k = 0; k < 16; ++k) if ((k & 2) && !(k & 1))     // CRX(5,7)
      CRXT_PAIR(Cr[k], Ci[k], Cr[k+1], Ci[k+1], tp, tn);
    {
      u64 tup = pk(t1u, t1u), tun = pk(-t1u, -t1u);
      u64 tdp = pk(t1d, t1d), tdn = pk(-t1d, -t1d);
#pragma unroll
      for (int k = 0; k < 16; ++k) if ((k & 4) && !(k & 2))   // CRX(3,5)
        CRXT_PAIR2(Cr[k], Ci[k], Cr[k+2], Ci[k+2], tup, tun, tdp, tdn);
    }

    {
      float Ars = __ldg(&g_uc[22]), Ais = __ldg(&g_uc[23]);
      float Ers = __ldg(&g_uc[24]), Eis = __ldg(&g_uc[25]);
      float Cc  = __ldg(&g_uc[18]), Cs  = __ldg(&g_uc[19]);
      u64 pCc = pk(Cc, Cc), pCsn = pk(-Cs, -Cs), pCsp = pk(Cs, Cs);
      u64 sArn = pk(-Ars, -Ars), sAip = pk(Ais, Ais), sAin = pk(-Ais, -Ais);
      u64 sEr = pk(Ers, Ers), sEin = pk(-Eis, -Eis), sEip = pk(Eis, Eis);
#pragma unroll
      for (int k = 0; k < 16; ++k) if (!(k & 4))              // U3 q3 (scaled)
        U3T_PAIR(Cr[k], Ci[k], Cr[k+4], Ci[k+4],
                 sArn, sAip, sAin, pCc, pCsn, pCsp, sEr, sEin, sEip);
    }
    {
      float Ar = __ldg(&g_uc[16]), Ai = __ldg(&g_uc[17]);
      float Er = __ldg(&g_uc[20]), Ei = __ldg(&g_uc[21]);
      float Cc = __ldg(&g_uc[18]), Cs = __ldg(&g_uc[19]);
      u64 pCc = pk(Cc, Cc), pCsn = pk(-Cs, -Cs), pCsp = pk(Cs, Cs);
      u64 uArn = pk(-Ar, -Ar), uAip = pk(Ai, Ai), uAin = pk(-Ai, -Ai);
      u64 uEr = pk(Er, Er), uEin = pk(-Ei, -Ei), uEip = pk(Ei, Ei);
#pragma unroll
      for (int k = 0; k < 16; ++k) if (!(k & 1))              // U3 q7
        U3T_PAIR(Cr[k], Ci[k], Cr[k+1], Ci[k+1],
                 uArn, uAip, uAin, pCc, pCsn, pCsp, uEr, uEin, uEip);
    }
  }

  // --- expval with deferred weights ---
  float c1sq = __ldg(&g_uc[27]);
  float c1q  = __ldg(&g_uc[28]);
  u64 pc2 = pk(c1sq, c1sq), pc4 = pk(c1q, c1q);

  u64 acc0 = pk(0.f, 0.f), acc1 = acc0, acc2 = acc0, acc3 = acc0;
#pragma unroll
  for (int k = 0; k < 16; ++k) {
    u64 pp = f2fma(Cr[k], Cr[k], f2mul(Ci[k], Ci[k]));
    const int nb = ((k >> 3) & 1) + ((k >> 1) & 1);
    if (nb == 1)      pp = f2mul(pp, pc2);
    else if (nb == 2) pp = f2mul(pp, pc4);
    int idx = ((k & 4) ? 2 : 0) | (k & 1);
    if      (idx == 0) acc0 = f2add(acc0, pp);
    else if (idx == 1) acc1 = f2add(acc1, pp);
    else if (idx == 2) acc2 = f2add(acc2, pp);
    else               acc3 = f2add(acc3, pp);
  }
  float c02 = __ldg(&g_uc[26]);
  float l, h, s0, s1, s2, s3;
  unpk(acc0, l, h); s0 = fmaf(c02, h, l);
  unpk(acc1, l, h); s1 = fmaf(c02, h, l);
  unpk(acc2, l, h); s2 = fmaf(c02, h, l);
  unpk(acc3, l, h); s3 = fmaf(c02, h, l);
  float z3 = (s0 + s1) - (s2 + s3);
  float z7 = (s0 + s2) - (s1 + s3);

  {
    float lw2 = 1.0f;
    if (g0) lw2 *= c02;
    if (g1) lw2 *= c02;
    if (g2) lw2 *= c02;
    z3 *= lw2;
    z7 *= lw2;
  }

  z3 += __shfl_xor_sync(FULLMASK, z3, 1);
  z3 += __shfl_xor_sync(FULLMASK, z3, 2);
  z3 += __shfl_xor_sync(FULLMASK, z3, 4);
  z7 += __shfl_xor_sync(FULLMASK, z7, 1);
  z7 += __shfl_xor_sync(FULLMASK, z7, 2);
  z7 += __shfl_xor_sync(FULLMASK, z7, 4);

  // --- MLP head, parallel over the 8 group lanes ---
  {
    float G2 = __ldg(&g_uc[29]);
    z3 *= G2;
    z7 *= G2;

    int j = g;
    float hh = tanhf(fmaf(z3, w1[j], fmaf(z7, w1[10 + j], b1[j])));
    float part = hh * w2[j];
    if (g < 2) {
      int j2 = 8 + g;
      float hh2 = tanhf(fmaf(z3, w1[j2], fmaf(z7, w1[10 + j2], b1[j2])));
      part = fmaf(hh2, w2[j2], part);
    }
    part += __shfl_xor_sync(FULLMASK, part, 1);
    part += __shfl_xor_sync(FULLMASK, part, 2);
    part += __shfl_xor_sync(FULLMASK, part, 4);

    if (g == 0)
      out[elem] = 1.0f / (1.0f + expf(-(part + b2[0])));
  }
}

extern "C" void kernel_launch(void* const* d_in, const int* in_sizes, int n_in,
                              void* d_out, int out_size) {
  const float* x   = (const float*)d_in[0];
  const float* crx = (const float*)d_in[1];
  const float* u3p = (const float*)d_in[2];
  const float* w1  = (const float*)d_in[3];
  const float* b1  = (const float*)d_in[4];
  const float* w2  = (const float*)d_in[5];
  const float* b2  = (const float*)d_in[6];
  float* out = (float*)d_out;

  qcnn_setup<<<1, 1>>>(crx, u3p);

  int B = in_sizes[0] / 8;
  int threads = B * 8;
  int block = 128;
  int grid = (threads + block - 1) / block;
  qcnn_kernel<<<grid, block>>>(x, w1, b1, w2, b2, out, B);
}